// round 11
// baseline (speedup 1.0000x reference)
#include <cuda_runtime.h>
#include <cstdint>

#define NB 128
#define NT 256
#define BZ 32
#define TT 2048
#define FF 128
#define HH 256
#define SLOT (BZ*HH)
#define MEMOFF ((TT+1)*SLOT)

// shared memory float offsets (R2-best layout)
#define O_SA 0                      // sa[32][385]  (x: k<128, h: k in [128,384))
#define O_CB (O_SA+32*385)          // cbuf[32][257]
#define O_WA (O_CB+32*257)          // WA[384][8]
#define O_WP (O_WA+384*8)           // WP[256][4]
#define O_WO (O_WP+256*4)           // WO[256][2]
#define O_BA (O_WO+256*2)           // ba[8]
#define O_BP (O_BA+8)               // bp[4]
#define O_BO (O_BP+4)               // bo[4]
#define O_PA (O_BO+4)               // PA[8][8][32]
#define O_PP (O_PA+2048)            // PP[8][4][32]
#define O_PO (O_PP+1024)            // PO[8][2][32]
#define O_YA (O_PO+512)             // yA[8][32]
#define O_YP (O_YA+256)             // yP[4][32]
#define O_OP (O_YP+128)             // o preact [2][32]
#define SMF  (O_OP+64)
#define SMB  (SMF*4)

// per-CTA epoch flags: [0:128) = c barrier, [128:256) = h barrier
__device__ unsigned g_fl[256];

__device__ __forceinline__ float sgm(float v){ return 1.f/(1.f+expf(-v)); }

// contention-free grid barrier: per-CTA release-store + coalesced poll
__device__ __forceinline__ void farrive(unsigned* f, unsigned val){
  __syncthreads();                       // all this CTA's STGs done
  if (threadIdx.x==0)
    asm volatile("st.release.gpu.u32 [%0], %1;" :: "l"(f+blockIdx.x), "r"(val) : "memory");
}
__device__ __forceinline__ void fwait(const unsigned* f, unsigned tgt){
  if (threadIdx.x < 32){
    unsigned ok;
    do {
      ok = 1u;
      #pragma unroll
      for (int j=0;j<4;j++){
        unsigned v;
        asm volatile("ld.acquire.gpu.u32 %0,[%1];" : "=r"(v) : "l"(f+threadIdx.x*4+j) : "memory");
        if (v < tgt) ok = 0u;
      }
    } while(!__all_sync(0xffffffffu, ok));
  }
  __syncthreads();
}

__global__ void zk(float* __restrict__ out){
  int i = blockIdx.x*blockDim.x + threadIdx.x;
  if (i < 256) g_fl[i] = 0u;
  if (i < SLOT){ out[i]=0.f; out[MEMOFF+i]=0.f; }   // h0 = c0 = 0
}

__global__ void __launch_bounds__(NT,1) lstm(
  const float* __restrict__ x,  const float* __restrict__ Wx,  const float* __restrict__ bx,
  const float* __restrict__ Wh, const float* __restrict__ bh,
  const float* __restrict__ Wci,const float* __restrict__ bci,
  const float* __restrict__ Wcf,const float* __restrict__ bcf,
  const float* __restrict__ Wco,const float* __restrict__ bco,
  float* __restrict__ out)
{
  extern __shared__ float sm[];
  const int tid=threadIdx.x, warp=tid>>5, lane=tid&31;
  const int j0 = blockIdx.x*2;

  // ---- one-time weight staging ----
  for (int i=tid; i<384*8; i+=NT){
    int k=i>>3, r=i&7, u=r>>2, q=r&3, g=q*HH+j0+u;
    sm[O_WA+i] = (k<FF) ? Wx[g*FF+k] : Wh[g*HH+k-FF];
  }
  for (int i=tid; i<256*4; i+=NT){
    int k=i>>2, r=i&3, u=r>>1, p=r&1;
    sm[O_WP+i] = (p?Wcf:Wci)[(j0+u)*HH+k];
  }
  for (int i=tid; i<256*2; i+=NT){
    int k=i>>1, u=i&1; sm[O_WO+i] = Wco[(j0+u)*HH+k];
  }
  if (tid<8){ int u=tid>>2,q=tid&3,g=q*HH+j0+u; sm[O_BA+tid]=bx[g]+bh[g]; }
  else if (tid<12){ int r=tid-8,u=r>>1; sm[O_BP+r]=((r&1)?bcf:bci)[j0+u]; }
  else if (tid<14){ sm[O_BO+tid-12]=bco[j0+tid-12]; }

  // c0 = 0 in smem
  for (int i=tid; i<32*257; i+=NT) sm[O_CB+i]=0.f;

  float* hid = out;
  float* mem = out + MEMOFF;

  // stage x(0): 1024 float4, 4 per thread
  #pragma unroll
  for (int it=0; it<4; it++){
    int idx=tid+it*NT, b=idx>>5, f=idx&31;
    float4 v = *(const float4*)(x + ((long)b*TT + 0)*FF + f*4);
    float* d = sm + O_SA + b*385 + f*4;
    d[0]=v.x; d[1]=v.y; d[2]=v.z; d[3]=v.w;
  }

  for (int s=0; s<TT; s++){
    // ---- stage h(s): 2048 float4, 8 per thread ----
    #pragma unroll
    for (int it=0; it<8; it++){
      int idx=tid+it*NT, b=idx>>6, f=idx&63;
      float4 v = *(const float4*)(hid + (long)s*SLOT + b*HH + f*4);
      float* d = sm + O_SA + b*385 + FF + f*4;
      d[0]=v.x; d[1]=v.y; d[2]=v.z; d[3]=v.w;
    }
    __syncthreads();

    // ---- phase A: 8 gate rows, K=384 (x|h), lane=batch, warp=k-chunk of 48 ----
    float acc[8];
    #pragma unroll
    for (int r=0;r<8;r++) acc[r]=0.f;
    for (int k=warp*48; k<warp*48+48; k++){
      float sv = sm[O_SA + lane*385 + k];
      float4 w0 = *(float4*)&sm[O_WA + k*8];
      float4 w1 = *(float4*)&sm[O_WA + k*8+4];
      acc[0]+=w0.x*sv; acc[1]+=w0.y*sv; acc[2]+=w0.z*sv; acc[3]+=w0.w*sv;
      acc[4]+=w1.x*sv; acc[5]+=w1.y*sv; acc[6]+=w1.z*sv; acc[7]+=w1.w*sv;
    }
    #pragma unroll
    for (int r=0;r<8;r++) sm[O_PA + warp*256 + r*32 + lane] = acc[r];

    // peephole dots over c (K=256)
    float ap[4];
    #pragma unroll
    for (int r=0;r<4;r++) ap[r]=0.f;
    for (int k=warp*32; k<warp*32+32; k++){
      float cv = sm[O_CB + lane*257 + k];
      float4 w = *(float4*)&sm[O_WP + k*4];
      ap[0]+=w.x*cv; ap[1]+=w.y*cv; ap[2]+=w.z*cv; ap[3]+=w.w*cv;
    }
    #pragma unroll
    for (int r=0;r<4;r++) sm[O_PP + warp*128 + r*32 + lane] = ap[r];

    // prefetch x(s+1) into registers (latency hidden under reduce phase)
    float4 xp[4];
    if (s+1<TT){
      #pragma unroll
      for (int it=0; it<4; it++){
        int idx=tid+it*NT, b=idx>>5, f=idx&31;
        xp[it] = *(const float4*)(x + ((long)b*TT + (s+1))*FF + f*4);
      }
    }
    __syncthreads();

    // ---- cross-warp reduce ----
    {
      int r=tid>>5, b=lane;
      float v = sm[O_BA+r];
      #pragma unroll
      for (int w=0;w<8;w++) v += sm[O_PA + w*256 + r*32 + b];
      sm[O_YA + r*32 + b] = v;
    }
    if (tid<128){
      int r=tid>>5, b=lane;
      float v = sm[O_BP+r];
      #pragma unroll
      for (int w=0;w<8;w++) v += sm[O_PP + w*128 + r*32 + b];
      sm[O_YP + r*32 + b] = v;
    }
    __syncthreads();

    // ---- gates, c_new ----
    if (tid<64){
      int u=tid>>5, b=lane;
      float ii = sgm (sm[O_YA+(u*4+0)*32+b] + sm[O_YP+(u*2+0)*32+b]);
      float ff = sgm (sm[O_YA+(u*4+1)*32+b] + sm[O_YP+(u*2+1)*32+b]);
      float gg = tanhf(sm[O_YA+(u*4+3)*32+b]);
      float co = sm[O_CB + b*257 + j0+u];
      float cn = ff*co + ii*gg;
      mem[(long)(s+1)*SLOT + b*HH + j0+u] = cn;
      sm[O_OP + u*32 + b] = sm[O_YA+(u*4+2)*32+b];
    }
    farrive(g_fl, (unsigned)(s+1));        // c_new pushed
    fwait(g_fl, (unsigned)(s+1));          // all CTAs' c_new visible

    // ---- stage full c_new ----
    #pragma unroll
    for (int it=0; it<8; it++){
      int idx=tid+it*NT, b=idx>>6, f=idx&63;
      float4 v = *(const float4*)(mem + (long)(s+1)*SLOT + b*HH + f*4);
      float* d = sm + O_CB + b*257 + f*4;
      d[0]=v.x; d[1]=v.y; d[2]=v.z; d[3]=v.w;
    }
    __syncthreads();

    // ---- phase B: o-gate peephole over c_new ----
    float ao0=0.f, ao1=0.f;
    for (int k=warp*32; k<warp*32+32; k++){
      float cv = sm[O_CB + lane*257 + k];
      float2 w = *(float2*)&sm[O_WO + k*2];
      ao0 += w.x*cv; ao1 += w.y*cv;
    }
    sm[O_PO + warp*64 + lane]      = ao0;
    sm[O_PO + warp*64 + 32 + lane] = ao1;
    __syncthreads();
    if (tid<64){
      int u=tid>>5, b=lane;
      float v = sm[O_BO+u] + sm[O_OP + u*32 + b];
      #pragma unroll
      for (int w=0;w<8;w++) v += sm[O_PO + w*64 + u*32 + b];
      float oo = sgm(v);
      float cn = sm[O_CB + b*257 + j0+u];
      hid[(long)(s+1)*SLOT + b*HH + j0+u] = oo*tanhf(cn);
    }

    // ---- store prefetched x(s+1) (x region dead until next phase A) ----
    if (s+1<TT){
      #pragma unroll
      for (int it=0; it<4; it++){
        int idx=tid+it*NT, b=idx>>5, f=idx&31;
        float* d = sm + O_SA + b*385 + f*4;
        float4 v = xp[it];
        d[0]=v.x; d[1]=v.y; d[2]=v.z; d[3]=v.w;
      }
    }
    farrive(g_fl+128, (unsigned)(s+1));    // h_new pushed
    fwait(g_fl+128, (unsigned)(s+1));      // all CTAs' h_new visible
  }
}

extern "C" void kernel_launch(void* const* d_in, const int* in_sizes, int n_in,
                              void* d_out, int out_size) {
  cudaFuncSetAttribute(lstm, cudaFuncAttributeMaxDynamicSharedMemorySize, SMB);
  float* out = (float*)d_out;
  zk<<<32, 256>>>(out);
  lstm<<<NB, NT, SMB>>>(
    (const float*)d_in[0], (const float*)d_in[1], (const float*)d_in[2],
    (const float*)d_in[3], (const float*)d_in[4],
    (const float*)d_in[5], (const float*)d_in[6],
    (const float*)d_in[7], (const float*)d_in[8],
    (const float*)d_in[9], (const float*)d_in[10],
    out);
}

// round 12
// speedup vs baseline: 3.5316x; 3.5316x over previous
#include <cuda_runtime.h>
#include <cstdint>

#define NB 128
#define NT 256
#define BZ 32
#define TT 2048
#define FF 128
#define HH 256
#define SLOT (BZ*HH)
#define MEMOFF ((TT+1)*SLOT)

// shared memory float offsets (R2 layout)
#define O_SA 0                      // sa[32][385]  (x: k<128, h: k in [128,384))
#define O_CB (O_SA+32*385)          // cbuf[32][257]
#define O_WA (O_CB+32*257)          // WA[384][8]
#define O_WP (O_WA+384*8)           // WP[256][4]
#define O_WO (O_WP+256*4)           // WO[256][2]
#define O_BA (O_WO+256*2)           // ba[8]
#define O_BP (O_BA+8)               // bp[4]
#define O_BO (O_BP+4)               // bo[4]
#define O_PA (O_BO+4)               // PA[8][8][32]
#define O_PP (O_PA+2048)            // PP[8][4][32]
#define O_PO (O_PP+1024)            // PO[8][2][32]
#define O_YA (O_PO+512)             // yA[8][32]
#define O_YP (O_YA+256)             // yP[4][32]
#define O_OP (O_YP+128)             // o preact [2][32]
#define SMF  (O_OP+64)
#define SMB  (SMF*4)

// two counters, 128B apart (separate sectors for c- and h-pollers)
__device__ unsigned g_bar[64];

__device__ __forceinline__ float sgm(float v){ return 1.f/(1.f+expf(-v)); }

// arrive: release-RMW (no separate MEMBAR.GPU); cumulative over the syncthreads edge
__device__ __forceinline__ void farrive(unsigned* c){
  __syncthreads();
  if (threadIdx.x==0)
    asm volatile("red.release.gpu.global.add.u32 [%0], 1;" :: "l"(c) : "memory");
}
// wait: single polling thread per CTA (proven-best pattern)
__device__ __forceinline__ void fwait(unsigned* c, unsigned tgt){
  if (threadIdx.x==0){
    unsigned v;
    do { asm volatile("ld.acquire.gpu.u32 %0,[%1];" : "=r"(v) : "l"(c) : "memory"); } while (v < tgt);
  }
  __syncthreads();
}

__global__ void zk(float* __restrict__ out){
  int i = blockIdx.x*blockDim.x + threadIdx.x;
  if (i < 64) g_bar[i] = 0u;
  if (i < SLOT){ out[i]=0.f; out[MEMOFF+i]=0.f; }   // h0 = c0 = 0
}

__global__ void __launch_bounds__(NT,1) lstm(
  const float* __restrict__ x,  const float* __restrict__ Wx,  const float* __restrict__ bx,
  const float* __restrict__ Wh, const float* __restrict__ bh,
  const float* __restrict__ Wci,const float* __restrict__ bci,
  const float* __restrict__ Wcf,const float* __restrict__ bcf,
  const float* __restrict__ Wco,const float* __restrict__ bco,
  float* __restrict__ out)
{
  extern __shared__ float sm[];
  const int tid=threadIdx.x, warp=tid>>5, lane=tid&31;
  const int j0 = blockIdx.x*2;
  const int ro = blockIdx.x & 63;        // staging rotation (de-correlate L2 access order)

  // ---- one-time weight staging ----
  for (int i=tid; i<384*8; i+=NT){
    int k=i>>3, r=i&7, u=r>>2, q=r&3, g=q*HH+j0+u;
    sm[O_WA+i] = (k<FF) ? Wx[g*FF+k] : Wh[g*HH+k-FF];
  }
  for (int i=tid; i<256*4; i+=NT){
    int k=i>>2, r=i&3, u=r>>1, p=r&1;
    sm[O_WP+i] = (p?Wcf:Wci)[(j0+u)*HH+k];
  }
  for (int i=tid; i<256*2; i+=NT){
    int k=i>>1, u=i&1; sm[O_WO+i] = Wco[(j0+u)*HH+k];
  }
  if (tid<8){ int u=tid>>2,q=tid&3,g=q*HH+j0+u; sm[O_BA+tid]=bx[g]+bh[g]; }
  else if (tid<12){ int r=tid-8,u=r>>1; sm[O_BP+r]=((r&1)?bcf:bci)[j0+u]; }
  else if (tid<14){ sm[O_BO+tid-12]=bco[j0+tid-12]; }

  // c0 = 0 in smem
  for (int i=tid; i<32*257; i+=NT) sm[O_CB+i]=0.f;

  float* hid = out;
  float* mem = out + MEMOFF;

  // stage x(0): 1024 float4, 4 per thread
  #pragma unroll
  for (int it=0; it<4; it++){
    int idx=tid+it*NT, b=idx>>5, f=idx&31;
    float4 v = *(const float4*)(x + ((long)b*TT + 0)*FF + f*4);
    float* d = sm + O_SA + b*385 + f*4;
    d[0]=v.x; d[1]=v.y; d[2]=v.z; d[3]=v.w;
  }

  for (int s=0; s<TT; s++){
    // ---- stage h(s): 2048 float4, 8 per thread, rotated start ----
    #pragma unroll
    for (int it=0; it<8; it++){
      int idx=tid+it*NT, b=idx>>6, f=(idx+ro)&63;
      float4 v = *(const float4*)(hid + (long)s*SLOT + b*HH + f*4);
      float* d = sm + O_SA + b*385 + FF + f*4;
      d[0]=v.x; d[1]=v.y; d[2]=v.z; d[3]=v.w;
    }
    __syncthreads();

    // ---- phase A: 8 gate rows, K=384 (x|h), lane=batch, warp=k-chunk of 48 ----
    float acc[8];
    #pragma unroll
    for (int r=0;r<8;r++) acc[r]=0.f;
    for (int k=warp*48; k<warp*48+48; k++){
      float sv = sm[O_SA + lane*385 + k];
      float4 w0 = *(float4*)&sm[O_WA + k*8];
      float4 w1 = *(float4*)&sm[O_WA + k*8+4];
      acc[0]+=w0.x*sv; acc[1]+=w0.y*sv; acc[2]+=w0.z*sv; acc[3]+=w0.w*sv;
      acc[4]+=w1.x*sv; acc[5]+=w1.y*sv; acc[6]+=w1.z*sv; acc[7]+=w1.w*sv;
    }
    #pragma unroll
    for (int r=0;r<8;r++) sm[O_PA + warp*256 + r*32 + lane] = acc[r];

    // peephole dots over c (K=256)
    float ap[4];
    #pragma unroll
    for (int r=0;r<4;r++) ap[r]=0.f;
    for (int k=warp*32; k<warp*32+32; k++){
      float cv = sm[O_CB + lane*257 + k];
      float4 w = *(float4*)&sm[O_WP + k*4];
      ap[0]+=w.x*cv; ap[1]+=w.y*cv; ap[2]+=w.z*cv; ap[3]+=w.w*cv;
    }
    #pragma unroll
    for (int r=0;r<4;r++) sm[O_PP + warp*128 + r*32 + lane] = ap[r];

    // prefetch x(s+1) into registers (latency hidden under reduces/gates)
    float4 xp[4];
    if (s+1<TT){
      #pragma unroll
      for (int it=0; it<4; it++){
        int idx=tid+it*NT, b=idx>>5, f=idx&31;
        xp[it] = *(const float4*)(x + ((long)b*TT + (s+1))*FF + f*4);
      }
    }
    __syncthreads();

    // ---- cross-warp reduce ----
    {
      int r=tid>>5, b=lane;
      float v = sm[O_BA+r];
      #pragma unroll
      for (int w=0;w<8;w++) v += sm[O_PA + w*256 + r*32 + b];
      sm[O_YA + r*32 + b] = v;
    }
    if (tid<128){
      int r=tid>>5, b=lane;
      float v = sm[O_BP+r];
      #pragma unroll
      for (int w=0;w<8;w++) v += sm[O_PP + w*128 + r*32 + b];
      sm[O_YP + r*32 + b] = v;
    }
    __syncthreads();

    // ---- gates, c_new ----
    if (tid<64){
      int u=tid>>5, b=lane;
      float ii = sgm (sm[O_YA+(u*4+0)*32+b] + sm[O_YP+(u*2+0)*32+b]);
      float ff = sgm (sm[O_YA+(u*4+1)*32+b] + sm[O_YP+(u*2+1)*32+b]);
      float gg = tanhf(sm[O_YA+(u*4+3)*32+b]);
      float co = sm[O_CB + b*257 + j0+u];
      float cn = ff*co + ii*gg;
      mem[(long)(s+1)*SLOT + b*HH + j0+u] = cn;
      sm[O_OP + u*32 + b] = sm[O_YA+(u*4+2)*32+b];
    }
    farrive(&g_bar[0]);
    fwait(&g_bar[0], (unsigned)(s+1)*NB);    // all CTAs' c_new visible

    // ---- stage full c_new (rotated) ----
    #pragma unroll
    for (int it=0; it<8; it++){
      int idx=tid+it*NT, b=idx>>6, f=(idx+ro)&63;
      float4 v = *(const float4*)(mem + (long)(s+1)*SLOT + b*HH + f*4);
      float* d = sm + O_CB + b*257 + f*4;
      d[0]=v.x; d[1]=v.y; d[2]=v.z; d[3]=v.w;
    }
    __syncthreads();

    // ---- phase B: o-gate peephole over c_new ----
    float ao0=0.f, ao1=0.f;
    for (int k=warp*32; k<warp*32+32; k++){
      float cv = sm[O_CB + lane*257 + k];
      float2 w = *(float2*)&sm[O_WO + k*2];
      ao0 += w.x*cv; ao1 += w.y*cv;
    }
    sm[O_PO + warp*64 + lane]      = ao0;
    sm[O_PO + warp*64 + 32 + lane] = ao1;
    __syncthreads();
    if (tid<64){
      int u=tid>>5, b=lane;
      float v = sm[O_BO+u] + sm[O_OP + u*32 + b];
      #pragma unroll
      for (int w=0;w<8;w++) v += sm[O_PO + w*64 + u*32 + b];
      float oo = sgm(v);
      float cn = sm[O_CB + b*257 + j0+u];
      hid[(long)(s+1)*SLOT + b*HH + j0+u] = oo*tanhf(cn);
    }

    // ---- store prefetched x(s+1) (x region dead until next phase A) ----
    if (s+1<TT){
      #pragma unroll
      for (int it=0; it<4; it++){
        int idx=tid+it*NT, b=idx>>5, f=idx&31;
        float* d = sm + O_SA + b*385 + f*4;
        float4 v = xp[it];
        d[0]=v.x; d[1]=v.y; d[2]=v.z; d[3]=v.w;
      }
    }
    farrive(&g_bar[32]);
    fwait(&g_bar[32], (unsigned)(s+1)*NB);   // all CTAs' h_new visible
  }
}

extern "C" void kernel_launch(void* const* d_in, const int* in_sizes, int n_in,
                              void* d_out, int out_size) {
  cudaFuncSetAttribute(lstm, cudaFuncAttributeMaxDynamicSharedMemorySize, SMB);
  float* out = (float*)d_out;
  zk<<<32, 256>>>(out);
  lstm<<<NB, NT, SMB>>>(
    (const float*)d_in[0], (const float*)d_in[1], (const float*)d_in[2],
    (const float*)d_in[3], (const float*)d_in[4],
    (const float*)d_in[5], (const float*)d_in[6],
    (const float*)d_in[7], (const float*)d_in[8],
    (const float*)d_in[9], (const float*)d_in[10],
    out);
}

// round 13
// speedup vs baseline: 4.6053x; 1.3040x over previous
#include <cuda_runtime.h>
#include <cstdint>

#define NB 128
#define NT 256
#define BZ 32
#define TT 2048
#define FF 128
#define HH 256
#define SLOT (BZ*HH)
#define MEMOFF ((TT+1)*SLOT)

// shared memory float offsets (weights + partials only; no state staging)
#define O_WA 0                      // WA[384][8]   r=u*4+q
#define O_WP (O_WA+384*8)           // WP[256][4]   r=u*2+p
#define O_WO (O_WP+256*4)           // WO[256][2]
#define O_BA (O_WO+256*2)           // ba[8]
#define O_BP (O_BA+8)               // bp[4]
#define O_BO (O_BP+4)               // bo[4]
#define O_PA (O_BO+4)               // PA[8][8][32]
#define O_PP (O_PA+2048)            // PP[8][4][32]
#define O_PO (O_PP+1024)            // PO[8][2][32]
#define O_YA (O_PO+512)             // yA[8][32]
#define O_YP (O_YA+256)             // yP[4][32]
#define O_OP (O_YP+128)             // o preact [64]
#define O_CN (O_OP+64)              // own c_new [64]
#define SMF  (O_CN+64)
#define SMB  (SMF*4)

// transposed state mirrors (batch-minor => coalesced lane=batch reads)
__device__ float xTg[(long)TT*FF*BZ];   // [t][f][b]
__device__ float hTg[2][HH*BZ];         // [parity][u][b]
__device__ float cTg[2][HH*BZ];
__device__ unsigned g_bar[64];          // [0]=c counter, [32]=h counter

__device__ __forceinline__ float sgm(float v){ return 1.f/(1.f+expf(-v)); }

__device__ __forceinline__ void farrive(unsigned* c){
  __syncthreads();
  if (threadIdx.x==0)
    asm volatile("red.release.gpu.global.add.u32 [%0], 1;" :: "l"(c) : "memory");
}
__device__ __forceinline__ void fwait(unsigned* c, unsigned tgt){
  if (threadIdx.x==0){
    unsigned v;
    do { asm volatile("ld.acquire.gpu.u32 %0,[%1];" : "=r"(v) : "l"(c) : "memory"); } while (v < tgt);
  }
  __syncthreads();
}

__global__ void zk(float* __restrict__ out){
  int i = blockIdx.x*blockDim.x + threadIdx.x;
  if (i < 64) g_bar[i] = 0u;
  if (i < SLOT){
    out[i]=0.f; out[MEMOFF+i]=0.f;       // h0 = c0 = 0 in outputs
    hTg[0][i]=0.f; cTg[0][i]=0.f;        // parity-0 mirrors
  }
}

// x transpose: x[b][t][f] -> xT[t][f][b]
__global__ void tk(const float* __restrict__ x){
  __shared__ float tile[BZ][FF+1];
  int t = blockIdx.x;
  for (int idx=threadIdx.x; idx<BZ*FF; idx+=NT){
    int b=idx>>7, f=idx&127;
    tile[b][f] = x[((long)b*TT+t)*FF+f];
  }
  __syncthreads();
  for (int idx=threadIdx.x; idx<BZ*FF; idx+=NT){
    int f=idx>>5, b=idx&31;
    xTg[((long)t*FF+f)*BZ+b] = tile[b][f];
  }
}

__global__ void __launch_bounds__(NT,1) lstm(
  const float* __restrict__ x,  const float* __restrict__ Wx,  const float* __restrict__ bx,
  const float* __restrict__ Wh, const float* __restrict__ bh,
  const float* __restrict__ Wci,const float* __restrict__ bci,
  const float* __restrict__ Wcf,const float* __restrict__ bcf,
  const float* __restrict__ Wco,const float* __restrict__ bco,
  float* __restrict__ out)
{
  extern __shared__ float sm[];
  const int tid=threadIdx.x, warp=tid>>5, lane=tid&31;
  const int j0 = blockIdx.x*2;

  // ---- one-time weight staging (R2 layouts) ----
  for (int i=tid; i<384*8; i+=NT){
    int k=i>>3, r=i&7, u=r>>2, q=r&3, g=q*HH+j0+u;
    sm[O_WA+i] = (k<FF) ? Wx[g*FF+k] : Wh[g*HH+k-FF];
  }
  for (int i=tid; i<256*4; i+=NT){
    int k=i>>2, r=i&3, u=r>>1, p=r&1;
    sm[O_WP+i] = (p?Wcf:Wci)[(j0+u)*HH+k];
  }
  for (int i=tid; i<256*2; i+=NT){
    int k=i>>1, u=i&1; sm[O_WO+i] = Wco[(j0+u)*HH+k];
  }
  if (tid<8){ int u=tid>>2,q=tid&3,g=q*HH+j0+u; sm[O_BA+tid]=bx[g]+bh[g]; }
  else if (tid<12){ int r=tid-8,u=r>>1; sm[O_BP+r]=((r&1)?bcf:bci)[j0+u]; }
  else if (tid<14){ sm[O_BO+tid-12]=bco[j0+tid-12]; }
  __syncthreads();

  float* hid = out;
  float* mem = out + MEMOFF;

  for (int s=0; s<TT; s++){
    const int par = s&1, nxt = par^1;
    const float* __restrict__ cOld = cTg[par];
    float*       __restrict__ cNew = cTg[nxt];
    const float* __restrict__ hOld = hTg[par];
    float*       __restrict__ hNew = hTg[nxt];

    // issue c(s) loads BEFORE the h-wait (published at last step's c-barrier;
    // its buffer can't be overwritten until peers pass h-wait(s+1) — safe)
    float cv[32];
    #pragma unroll
    for (int kk=0;kk<32;kk++) cv[kk] = cOld[(warp*32+kk)*BZ + lane];
    float co_own = 0.f;
    if (tid<64) co_own = cOld[(j0+(tid>>5))*BZ + lane];

    if (s>0) fwait(&g_bar[32], (unsigned)s*NB);   // all h(s) mirrors visible

    // ---- phase A: 8 gate rows, K=384 (xT|hT), lane=batch, warp k-chunk 48 ----
    float a0=0,a1=0,a2=0,a3=0,a4=0,a5=0,a6=0,a7=0;
    #pragma unroll
    for (int half=0; half<2; half++){
      float sv[24];
      #pragma unroll
      for (int kk=0;kk<24;kk++){
        int k = warp*48 + half*24 + kk;
        sv[kk] = (k<FF) ? xTg[((long)s*FF+k)*BZ+lane] : hOld[(k-FF)*BZ+lane];
      }
      #pragma unroll
      for (int kk=0;kk<24;kk++){
        int k = warp*48 + half*24 + kk;
        float sval = sv[kk];
        float4 w0 = *(float4*)&sm[O_WA + k*8];
        float4 w1 = *(float4*)&sm[O_WA + k*8+4];
        a0+=w0.x*sval; a1+=w0.y*sval; a2+=w0.z*sval; a3+=w0.w*sval;
        a4+=w1.x*sval; a5+=w1.y*sval; a6+=w1.z*sval; a7+=w1.w*sval;
      }
    }
    sm[O_PA + warp*256 + 0*32 + lane]=a0; sm[O_PA + warp*256 + 1*32 + lane]=a1;
    sm[O_PA + warp*256 + 2*32 + lane]=a2; sm[O_PA + warp*256 + 3*32 + lane]=a3;
    sm[O_PA + warp*256 + 4*32 + lane]=a4; sm[O_PA + warp*256 + 5*32 + lane]=a5;
    sm[O_PA + warp*256 + 6*32 + lane]=a6; sm[O_PA + warp*256 + 7*32 + lane]=a7;

    // peephole i/f dots over c(s) from registers
    {
      float p0=0,p1=0,p2=0,p3=0;
      #pragma unroll
      for (int kk=0;kk<32;kk++){
        int k = warp*32 + kk;
        float4 w = *(float4*)&sm[O_WP + k*4];
        float cvv = cv[kk];
        p0+=w.x*cvv; p1+=w.y*cvv; p2+=w.z*cvv; p3+=w.w*cvv;
      }
      sm[O_PP + warp*128 + 0*32 + lane]=p0; sm[O_PP + warp*128 + 1*32 + lane]=p1;
      sm[O_PP + warp*128 + 2*32 + lane]=p2; sm[O_PP + warp*128 + 3*32 + lane]=p3;
    }
    __syncthreads();

    // ---- cross-warp reduce ----
    {
      int r=tid>>5, b=lane;
      float v = sm[O_BA+r];
      #pragma unroll
      for (int w=0;w<8;w++) v += sm[O_PA + w*256 + r*32 + b];
      sm[O_YA + r*32 + b] = v;
    }
    if (tid<128){
      int r=tid>>5, b=lane;
      float v = sm[O_BP+r];
      #pragma unroll
      for (int w=0;w<8;w++) v += sm[O_PP + w*128 + r*32 + b];
      sm[O_YP + r*32 + b] = v;
    }
    __syncthreads();

    // ---- gates, c_new ----
    if (tid<64){
      int u=tid>>5, b=lane;
      float ii = sgm (sm[O_YA+(u*4+0)*32+b] + sm[O_YP+(u*2+0)*32+b]);
      float ff = sgm (sm[O_YA+(u*4+1)*32+b] + sm[O_YP+(u*2+1)*32+b]);
      float gg = tanhf(sm[O_YA+(u*4+3)*32+b]);
      float cn = ff*co_own + ii*gg;
      mem[(long)(s+1)*SLOT + b*HH + j0+u] = cn;
      cNew[(j0+u)*BZ + b] = cn;               // transposed mirror (coalesced)
      sm[O_OP + tid] = sm[O_YA+(u*4+2)*32+b];
      sm[O_CN + tid] = cn;
    }
    farrive(&g_bar[0]);
    fwait(&g_bar[0], (unsigned)(s+1)*NB);      // all c_new mirrors visible

    // ---- phase B: o-peephole directly from cNew mirror ----
    {
      float ao0=0.f, ao1=0.f;
      #pragma unroll
      for (int kk=0;kk<32;kk++){
        int k = warp*32 + kk;
        float cvv = cNew[k*BZ + lane];
        float2 w = *(float2*)&sm[O_WO + k*2];
        ao0 += w.x*cvv; ao1 += w.y*cvv;
      }
      sm[O_PO + warp*64 + lane]      = ao0;
      sm[O_PO + warp*64 + 32 + lane] = ao1;
    }
    __syncthreads();
    if (tid<64){
      int u=tid>>5, b=lane;
      float v = sm[O_BO+u] + sm[O_OP + tid];
      #pragma unroll
      for (int w=0;w<8;w++) v += sm[O_PO + w*64 + u*32 + b];
      float oo = sgm(v);
      float cn = sm[O_CN + tid];
      float hn = oo*tanhf(cn);
      hid[(long)(s+1)*SLOT + b*HH + j0+u] = hn;
      hNew[(j0+u)*BZ + b] = hn;               // transposed mirror
    }
    farrive(&g_bar[32]);
    // h-wait at top of next step
  }
}

extern "C" void kernel_launch(void* const* d_in, const int* in_sizes, int n_in,
                              void* d_out, int out_size) {
  cudaFuncSetAttribute(lstm, cudaFuncAttributeMaxDynamicSharedMemorySize, SMB);
  float* out = (float*)d_out;
  const float* xin = (const float*)d_in[0];
  zk<<<32, 256>>>(out);
  tk<<<TT, NT>>>(xin);
  lstm<<<NB, NT, SMB>>>(
    xin, (const float*)d_in[1], (const float*)d_in[2],
    (const float*)d_in[3], (const float*)d_in[4],
    (const float*)d_in[5], (const float*)d_in[6],
    (const float*)d_in[7], (const float*)d_in[8],
    (const float*)d_in[9], (const float*)d_in[10],
    out);
}

// round 15
// speedup vs baseline: 5.3394x; 1.1594x over previous
#include <cuda_runtime.h>
#include <cstdint>

#define NB 128
#define NT 256
#define BZ 32
#define TT 2048
#define FF 128
#define HH 256
#define SLOT (BZ*HH)
#define MEMOFF ((TT+1)*SLOT)

// shared memory float offsets (weights + partials only)
#define O_WA 0                      // WA[384][8]   r=u*4+q (k<128 x, else h)
#define O_WP (O_WA+384*8)           // WP[256][4]   r=u*2+p
#define O_WO (O_WP+256*4)           // WO[256][2]
#define O_BA (O_WO+256*2)           // ba[8]
#define O_BP (O_BA+8)               // bp[4]
#define O_BO (O_BP+4)               // bo[4]
#define O_PA (O_BO+4)               // PA[8][8][32]
#define O_PP (O_PA+2048)            // PP[8][4][32]
#define O_PO (O_PP+1024)            // PO[8][2][32]
#define O_YA (O_PO+512)             // yA[8][32]
#define O_YP (O_YA+256)             // yP[4][32]
#define O_OP (O_YP+128)             // o preact [64]
#define O_CN (O_OP+64)              // own c_new [64]
#define SMF  (O_CN+64)
#define SMB  (SMF*4)

// transposed state mirrors (batch-minor)
__device__ float xTg[(long)TT*FF*BZ];   // [t][f][b]
__device__ float hTg[2][HH*BZ];         // [parity][u][b]
__device__ float cTg[2][HH*BZ];
__device__ unsigned g_bar[64];          // [0]=c counter, [32]=h counter

__device__ __forceinline__ float sgm(float v){ return 1.f/(1.f+expf(-v)); }

__device__ __forceinline__ void farrive(unsigned* c){
  __syncthreads();
  if (threadIdx.x==0)
    asm volatile("red.release.gpu.global.add.u32 [%0], 1;" :: "l"(c) : "memory");
}
__device__ __forceinline__ void fwait(unsigned* c, unsigned tgt){
  if (threadIdx.x==0){
    unsigned v;
    do { asm volatile("ld.acquire.gpu.u32 %0,[%1];" : "=r"(v) : "l"(c) : "memory"); } while (v < tgt);
  }
  __syncthreads();
}

__global__ void zk(float* __restrict__ out){
  int i = blockIdx.x*blockDim.x + threadIdx.x;
  if (i < 64) g_bar[i] = 0u;
  if (i < SLOT){
    out[i]=0.f; out[MEMOFF+i]=0.f;
    hTg[0][i]=0.f; cTg[0][i]=0.f;
  }
}

// x transpose: x[b][t][f] -> xT[t][f][b]
__global__ void tk(const float* __restrict__ x){
  __shared__ float tile[BZ][FF+1];
  int t = blockIdx.x;
  for (int idx=threadIdx.x; idx<BZ*FF; idx+=NT){
    int b=idx>>7, f=idx&127;
    tile[b][f] = x[((long)b*TT+t)*FF+f];
  }
  __syncthreads();
  for (int idx=threadIdx.x; idx<BZ*FF; idx+=NT){
    int f=idx>>5, b=idx&31;
    xTg[((long)t*FF+f)*BZ+b] = tile[b][f];
  }
}

// x-part of phase A: 16 k per warp (k = warp*16 + kk), accumulate 8 gate rows
__device__ __forceinline__ void xpart(const float* sm, int s, int warp, int lane, float* a){
  #pragma unroll
  for (int r=0;r<8;r++) a[r]=0.f;
  float sv[16];
  #pragma unroll
  for (int kk=0;kk<16;kk++)
    sv[kk] = xTg[((long)s*FF + warp*16 + kk)*BZ + lane];
  #pragma unroll
  for (int kk=0;kk<16;kk++){
    int k = warp*16 + kk;
    float4 w0 = *(float4*)&sm[O_WA + k*8];
    float4 w1 = *(float4*)&sm[O_WA + k*8+4];
    a[0]+=w0.x*sv[kk]; a[1]+=w0.y*sv[kk]; a[2]+=w0.z*sv[kk]; a[3]+=w0.w*sv[kk];
    a[4]+=w1.x*sv[kk]; a[5]+=w1.y*sv[kk]; a[6]+=w1.z*sv[kk]; a[7]+=w1.w*sv[kk];
  }
}

__global__ void __launch_bounds__(NT,1) lstm(
  const float* __restrict__ x,  const float* __restrict__ Wx,  const float* __restrict__ bx,
  const float* __restrict__ Wh, const float* __restrict__ bh,
  const float* __restrict__ Wci,const float* __restrict__ bci,
  const float* __restrict__ Wcf,const float* __restrict__ bcf,
  const float* __restrict__ Wco,const float* __restrict__ bco,
  float* __restrict__ out)
{
  extern __shared__ float sm[];
  const int tid=threadIdx.x, warp=tid>>5, lane=tid&31;
  const int j0 = blockIdx.x*2;

  // ---- one-time weight staging ----
  for (int i=tid; i<384*8; i+=NT){
    int k=i>>3, r=i&7, u=r>>2, q=r&3, g=q*HH+j0+u;
    sm[O_WA+i] = (k<FF) ? Wx[g*FF+k] : Wh[g*HH+k-FF];
  }
  for (int i=tid; i<256*4; i+=NT){
    int k=i>>2, r=i&3, u=r>>1, p=r&1;
    sm[O_WP+i] = (p?Wcf:Wci)[(j0+u)*HH+k];
  }
  for (int i=tid; i<256*2; i+=NT){
    int k=i>>1, u=i&1; sm[O_WO+i] = Wco[(j0+u)*HH+k];
  }
  if (tid<8){ int u=tid>>2,q=tid&3,g=q*HH+j0+u; sm[O_BA+tid]=bx[g]+bh[g]; }
  else if (tid<12){ int r=tid-8,u=r>>1; sm[O_BP+r]=((r&1)?bcf:bci)[j0+u]; }
  else if (tid<14){ sm[O_BO+tid-12]=bco[j0+tid-12]; }
  __syncthreads();

  float* hid = out;
  float* mem = out + MEMOFF;

  // x-part accumulators for s=0 (pipelined thereafter)
  float xa[8];
  xpart(sm, 0, warp, lane, xa);

  for (int s=0; s<TT; s++){
    const int par = s&1, nxt = par^1;
    const float* __restrict__ cOld = cTg[par];
    float*       __restrict__ cNew = cTg[nxt];
    const float* __restrict__ hOld = hTg[par];
    float*       __restrict__ hNew = hTg[nxt];

    // ---- pre-h-wait work: c(s)-dependent (published one barrier ago, safe) ----
    float cv[32];
    #pragma unroll
    for (int kk=0;kk<32;kk++) cv[kk] = cOld[(warp*32+kk)*BZ + lane];
    float co_own = 0.f;
    if (tid<64) co_own = cOld[(j0+(tid>>5))*BZ + lane];

    // peephole i/f partials (overlap h-barrier skew)
    {
      float p0=0,p1=0,p2=0,p3=0;
      #pragma unroll
      for (int kk=0;kk<32;kk++){
        int k = warp*32 + kk;
        float4 w = *(float4*)&sm[O_WP + k*4];
        p0+=w.x*cv[kk]; p1+=w.y*cv[kk]; p2+=w.z*cv[kk]; p3+=w.w*cv[kk];
      }
      sm[O_PP + warp*128 + 0*32 + lane]=p0; sm[O_PP + warp*128 + 1*32 + lane]=p1;
      sm[O_PP + warp*128 + 2*32 + lane]=p2; sm[O_PP + warp*128 + 3*32 + lane]=p3;
    }

    if (s>0) fwait(&g_bar[32], (unsigned)s*NB);   // all h(s) mirrors visible

    // ---- h-part of phase A: 32 k per warp into xa ----
    {
      float sv[32];
      #pragma unroll
      for (int kk=0;kk<32;kk++)
        sv[kk] = hOld[(warp*32+kk)*BZ + lane];
      #pragma unroll
      for (int kk=0;kk<32;kk++){
        int k = FF + warp*32 + kk;
        float4 w0 = *(float4*)&sm[O_WA + k*8];
        float4 w1 = *(float4*)&sm[O_WA + k*8+4];
        xa[0]+=w0.x*sv[kk]; xa[1]+=w0.y*sv[kk]; xa[2]+=w0.z*sv[kk]; xa[3]+=w0.w*sv[kk];
        xa[4]+=w1.x*sv[kk]; xa[5]+=w1.y*sv[kk]; xa[6]+=w1.z*sv[kk]; xa[7]+=w1.w*sv[kk];
      }
    }
    #pragma unroll
    for (int r=0;r<8;r++) sm[O_PA + warp*256 + r*32 + lane] = xa[r];
    __syncthreads();

    // ---- cross-warp reduce ----
    {
      int r=tid>>5, b=lane;
      float v = sm[O_BA+r];
      #pragma unroll
      for (int w=0;w<8;w++) v += sm[O_PA + w*256 + r*32 + b];
      sm[O_YA + r*32 + b] = v;
    }
    if (tid<128){
      int r=tid>>5, b=lane;
      float v = sm[O_BP+r];
      #pragma unroll
      for (int w=0;w<8;w++) v += sm[O_PP + w*128 + r*32 + b];
      sm[O_YP + r*32 + b] = v;
    }
    __syncthreads();

    // ---- gates, c_new ----
    if (tid<64){
      int u=tid>>5, b=lane;
      float ii = sgm (sm[O_YA+(u*4+0)*32+b] + sm[O_YP+(u*2+0)*32+b]);
      float ff = sgm (sm[O_YA+(u*4+1)*32+b] + sm[O_YP+(u*2+1)*32+b]);
      float gg = tanhf(sm[O_YA+(u*4+3)*32+b]);
      float cn = ff*co_own + ii*gg;
      mem[(long)(s+1)*SLOT + b*HH + j0+u] = cn;
      cNew[(j0+u)*BZ + b] = cn;
      sm[O_OP + tid] = sm[O_YA+(u*4+2)*32+b];
      sm[O_CN + tid] = cn;
    }
    farrive(&g_bar[0]);

    // ---- hidden under c-wait: x-part of NEXT step's phase A ----
    if (s+1<TT) xpart(sm, s+1, warp, lane, xa);

    fwait(&g_bar[0], (unsigned)(s+1)*NB);      // all c_new mirrors visible

    // ---- phase B: o-peephole from cNew mirror ----
    {
      float ao0=0.f, ao1=0.f;
      float cvv[32];
      #pragma unroll
      for (int kk=0;kk<32;kk++)
        cvv[kk] = cNew[(warp*32+kk)*BZ + lane];
      #pragma unroll
      for (int kk=0;kk<32;kk++){
        int k = warp*32 + kk;
        float2 w = *(float2*)&sm[O_WO + k*2];
        ao0 += w.x*cvv[kk]; ao1 += w.y*cvv[kk];
      }
      sm[O_PO + warp*64 + lane]      = ao0;
      sm[O_PO + warp*64 + 32 + lane] = ao1;
    }
    __syncthreads();
    if (tid<64){
      int u=tid>>5, b=lane;
      float v = sm[O_BO+u] + sm[O_OP + tid];
      #pragma unroll
      for (int w=0;w<8;w++) v += sm[O_PO + w*64 + u*32 + b];
      float oo = sgm(v);
      float cn = sm[O_CN + tid];
      float hn = oo*tanhf(cn);
      hid[(long)(s+1)*SLOT + b*HH + j0+u] = hn;
      hNew[(j0+u)*BZ + b] = hn;
    }
    farrive(&g_bar[32]);
    // h-wait at top of next step
  }
}

extern "C" void kernel_launch(void* const* d_in, const int* in_sizes, int n_in,
                              void* d_out, int out_size) {
  cudaFuncSetAttribute(lstm, cudaFuncAttributeMaxDynamicSharedMemorySize, SMB);
  float* out = (float*)d_out;
  const float* xin = (const float*)d_in[0];
  zk<<<32, 256>>>(out);
  tk<<<TT, NT>>>(xin);
  lstm<<<NB, NT, SMB>>>(
    xin, (const float*)d_in[1], (const float*)d_in[2],
    (const float*)d_in[3], (const float*)d_in[4],
    (const float*)d_in[5], (const float*)d_in[6],
    (const float*)d_in[7], (const float*)d_in[8],
    (const float*)d_in[9], (const float*)d_in[10],
    out);
}